// round 17
// baseline (speedup 1.0000x reference)
#include <cuda_runtime.h>
#include <math.h>

#define T_STEPS 512
#define B_DIM   64
#define DIN     1024
#define DH      1024
#define BN_EPS  1e-5f

#define NCTA        128
#define COLS_PER_CTA 8     // 1024 / 128
#define NTHREADS    1024   // 32 warps: 16 recurrence (R) + 16 input-gemm (G)
#define NRWARPS     16
#define K_PER_WARP  64     // 1024 / 16

// named barriers
#define BAR_SYNC(id, cnt)   asm volatile("bar.sync %0, %1;"   :: "r"(id), "r"(cnt) : "memory")
#define BAR_ARRIVE(id, cnt) asm volatile("bar.arrive %0, %1;" :: "r"(id), "r"(cnt) : "memory")
// id 1+p : gsum buf p FULL     (G arrives 512, R syncs 512, count 1024)
// id 3+p : gsum buf p CONSUMED (R arrives 512, G syncs 512, count 1024)
// id 5   : R-group internal    (count 512)
// id 6   : G-group internal    (count 512)

// packed fp32x2 ops
#define FMA_F32X2(d, a, b, c) \
    asm("fma.rn.f32x2 %0, %1, %2, %3;" : "=l"(d) : "l"(a), "l"(b), "l"(c))
#define DUP_F32X2(out, f) \
    asm("mov.b64 %0, {%1, %1};" : "=l"(out) : "r"(__float_as_uint(f)))

// cp.async (LDGSTS) helpers — .cg = L2-cached, L1-bypassed (state is cross-SM coherent via L2)
#define CP_ASYNC16(dst_u32, src_ptr) \
    asm volatile("cp.async.cg.shared.global [%0], [%1], 16;" :: "r"(dst_u32), "l"(src_ptr) : "memory")
#define CP_COMMIT() asm volatile("cp.async.commit_group;" ::: "memory")
#define CP_WAIT(n)  asm volatile("cp.async.wait_group %0;" :: "n"(n) : "memory")

// dynamic smem layout (floats):
#define OFF_WH    0        // [1024*8]  Wh slab
#define OFF_WX    8192     // [1024*8]  Wx slab
#define OFF_RPART 16384    // [16*512]  R split-K partials
#define OFF_GPART 24576    // [16*512]  G split-K partials (single, G-private)
#define OFF_GSUM  32768    // [2][512]  G pre-reduced xp (handoff ring)
#define OFF_H     33792    // [512]     h / normalized values
#define OFF_BIAS  34304    // [8] (+pad)
#define OFF_STAGE 34312    // [16 warps][2 bufs][512] cp.async state staging
#define SMEM_FLOATS (34312 + 16384)
#define SMEM_BYTES  (SMEM_FLOATS * 4)   // 202,784 B

// ---------------- scratch (no cudaMalloc allowed) ----------------
__device__ float g_xt[(size_t)T_STEPS * DIN * B_DIM];          // XT[t][k][b]
__device__ __align__(256) float g_stateT[2][DH * B_DIM];       // [j][b] transposed state
__device__ unsigned int g_bar_count = 0;
__device__ volatile unsigned int g_bar_gen = 0;

// ---------------- kernel 0: XT[t][k][b] = X[t][b][k] ----------------
__global__ void __launch_bounds__(256) transpose_x_kernel(
    const float* __restrict__ X,   // [T][B][DIN]
    float* __restrict__ XT)        // [T][DIN][B]
{
    __shared__ float tile[32][33];
    const int tx = threadIdx.x;
    const int ty = threadIdx.y;
    const int kt = blockIdx.x * 32;
    const int bt = blockIdx.y * 32;
    const int t  = blockIdx.z;

    const float* src = X + ((size_t)t * B_DIM + bt) * DIN + kt;
#pragma unroll
    for (int i = 0; i < 32; i += 8)
        tile[ty + i][tx] = src[(size_t)(ty + i) * DIN + tx];
    __syncthreads();

    float* dst = XT + ((size_t)t * DIN + kt) * B_DIM + bt;
#pragma unroll
    for (int i = 0; i < 32; i += 8)
        dst[(size_t)(ty + i) * B_DIM + tx] = tile[tx][ty + i];
}

// ---------------- G-warp body: xp partials (direct __ldg; latency covered by G slack) ----------------
__device__ __forceinline__ void g_compute(
    const float* __restrict__ xt_t,   // [k][b]
    const float* __restrict__ s_wx,   // [k][8]
    float* __restrict__ s_gp,         // [16][512]
    int gw, int lane)
{
    unsigned long long acc[8];
#pragma unroll
    for (int i = 0; i < 8; i++) acc[i] = 0ULL;

    const int b0 = lane * 2;
    const int k0 = gw * K_PER_WARP;
#pragma unroll 8
    for (int k = k0; k < k0 + K_PER_WARP; k++) {
        float2 xv = __ldg((const float2*)(xt_t + (size_t)k * B_DIM + b0));
        unsigned long long sx, sy;
        DUP_F32X2(sx, xv.x);
        DUP_F32X2(sy, xv.y);
        ulonglong2 w01 = *(const ulonglong2*)&s_wx[k * 8];
        ulonglong2 w23 = *(const ulonglong2*)&s_wx[k * 8 + 4];
        FMA_F32X2(acc[0], w01.x, sx, acc[0]);
        FMA_F32X2(acc[1], w01.y, sx, acc[1]);
        FMA_F32X2(acc[2], w23.x, sx, acc[2]);
        FMA_F32X2(acc[3], w23.y, sx, acc[3]);
        FMA_F32X2(acc[4], w01.x, sy, acc[4]);
        FMA_F32X2(acc[5], w01.y, sy, acc[5]);
        FMA_F32X2(acc[6], w23.x, sy, acc[6]);
        FMA_F32X2(acc[7], w23.y, sy, acc[7]);
    }
    ulonglong2* dst = (ulonglong2*)&s_gp[gw * 512 + lane * 16];
#pragma unroll
    for (int q = 0; q < 4; q++) {
        ulonglong2 v; v.x = acc[2 * q]; v.y = acc[2 * q + 1];
        dst[q] = v;
    }
}

// ---------------- R-warp body: cp.async-pipelined state GEMM ----------------
// warp k-range [warp*64, warp*64+64), 8 chunks of 8 k (2KB each), double-buffered in smem.
__device__ __forceinline__ void r_gemm_pipe(
    const float* __restrict__ st,     // [k][b] state (L2)
    const float* __restrict__ s_wh,   // [k][8]
    float* __restrict__ s_rpart,      // [16][512]
    float* __restrict__ s_stg,        // this warp's [2][512] staging
    int warp, int lane)
{
    const float* gsrc = st + (size_t)warp * (K_PER_WARP * B_DIM);   // 2KB chunks, contiguous
    const unsigned stg_base =
        (unsigned)__cvta_generic_to_shared(s_stg) + (unsigned)lane * 16u;

    // stage chunk c into buffer b: 4 x 16B per lane = 2KB per warp, contiguous
#define STAGE_CHUNK(c, bsel)                                              \
    do {                                                                  \
        const char* _s = (const char*)(gsrc + (c) * 512) + lane * 16;     \
        unsigned _d = stg_base + (unsigned)(bsel) * 2048u;                \
        CP_ASYNC16(_d + 0u,    _s + 0);                                   \
        CP_ASYNC16(_d + 512u,  _s + 512);                                 \
        CP_ASYNC16(_d + 1024u, _s + 1024);                                \
        CP_ASYNC16(_d + 1536u, _s + 1536);                                \
        CP_COMMIT();                                                      \
    } while (0)

    unsigned long long acc[8];
#pragma unroll
    for (int i = 0; i < 8; i++) acc[i] = 0ULL;

    STAGE_CHUNK(0, 0);
    STAGE_CHUNK(1, 1);

    const int b0 = lane * 2;
#pragma unroll
    for (int c = 0; c < 8; c++) {
        if (c < 7) { CP_WAIT(1); } else { CP_WAIT(0); }
        __syncwarp();                                  // cross-lane visibility of staged data

        const float* sb = s_stg + (c & 1) * 512;
        const float* wb = s_wh + (warp * K_PER_WARP + c * 8) * 8;
#pragma unroll
        for (int kk = 0; kk < 8; kk++) {
            float2 sv = *(const float2*)(sb + kk * 64 + b0);
            unsigned long long sx, sy;
            DUP_F32X2(sx, sv.x);
            DUP_F32X2(sy, sv.y);
            ulonglong2 w01 = *(const ulonglong2*)(wb + kk * 8);
            ulonglong2 w23 = *(const ulonglong2*)(wb + kk * 8 + 4);
            FMA_F32X2(acc[0], w01.x, sx, acc[0]);
            FMA_F32X2(acc[1], w01.y, sx, acc[1]);
            FMA_F32X2(acc[2], w23.x, sx, acc[2]);
            FMA_F32X2(acc[3], w23.y, sx, acc[3]);
            FMA_F32X2(acc[4], w01.x, sy, acc[4]);
            FMA_F32X2(acc[5], w01.y, sy, acc[5]);
            FMA_F32X2(acc[6], w23.x, sy, acc[6]);
            FMA_F32X2(acc[7], w23.y, sy, acc[7]);
        }
        __syncwarp();                                  // lanes done reading buf before restage
        if (c + 2 < 8) STAGE_CHUNK(c + 2, c & 1);
    }
#undef STAGE_CHUNK

    ulonglong2* dst = (ulonglong2*)&s_rpart[warp * 512 + lane * 16];
#pragma unroll
    for (int q = 0; q < 4; q++) {
        ulonglong2 v; v.x = acc[2 * q]; v.y = acc[2 * q + 1];
        dst[q] = v;
    }
}

// ---------------- kernel 1: fused persistent recurrence + decoupled input gemm ----------------
__global__ void __launch_bounds__(NTHREADS, 1) rnn_fused_kernel(
    const float* __restrict__ state0,  // [1][B][DH]
    const float* __restrict__ Wh,      // [DH][DH]
    const float* __restrict__ Wx,      // [DIN][DH]
    const float* __restrict__ bias,    // [DH]
    float* __restrict__ out,
    int out_elems)
{
    extern __shared__ float smem[];
    float* s_wh    = smem + OFF_WH;
    float* s_wx    = smem + OFF_WX;
    float* s_rpart = smem + OFF_RPART;
    float* s_gpart = smem + OFF_GPART;
    float* s_gsum  = smem + OFF_GSUM;    // [2][512]
    float* s_h     = smem + OFF_H;
    float* s_bias  = smem + OFF_BIAS;
    float* s_stage = smem + OFF_STAGE;   // [16][2][512]

    const int cta  = blockIdx.x;
    const int tid  = threadIdx.x;
    const int warp = tid >> 5;
    const int lane = tid & 31;
    const int j0   = cta * COLS_PER_CTA;

    // ---- stage weight slabs (ONCE) ----
    for (int i = tid; i < 2048; i += NTHREADS) {
        int k = i >> 1;
        int h = (i & 1) * 4;
        *(float4*)&s_wh[k * 8 + h] = __ldg((const float4*)(Wh + (size_t)k * DH + j0 + h));
        *(float4*)&s_wx[k * 8 + h] = __ldg((const float4*)(Wx + (size_t)k * DH + j0 + h));
    }
    if (tid < 8) s_bias[tid] = bias[j0 + tid];

    // init transposed state buffer 0 for our columns
    for (int o = tid; o < 512; o += NTHREADS) {
        int jj = o >> 6;
        int b  = o & 63;
        g_stateT[0][(j0 + jj) * B_DIM + b] = state0[(size_t)b * DH + j0 + jj];
    }
    __syncthreads();

    const long long half = (long long)T_STEPS * B_DIM * DH;
    const bool dup = ((long long)out_elems >= 2 * half);

    if (warp >= NRWARPS) {
        // ================= G-warps: free-running producer + pre-reduce =================
        const int gw    = warp - NRWARPS;
        const int g_tid = tid - 512;          // 0..511
        const int jj    = g_tid & 7;
        const int b     = g_tid >> 3;
        const int pi    = (b >> 1) * 16 + (b & 1) * 8 + jj;

        for (int tt = 0; tt < T_STEPS; tt++) {
            const int p = tt & 1;
            g_compute(g_xt + (size_t)tt * DIN * B_DIM, s_wx, s_gpart, gw, lane);
            BAR_SYNC(6, 512);                 // all G partials ready (drains STS)
            if (tt >= 2) BAR_SYNC(3 + p, 1024);   // gsum[p] consumed by R (step tt-2)
            {
                float z = 0.0f;
#pragma unroll
                for (int w = 0; w < NRWARPS; w++) z += s_gpart[w * 512 + pi];
                s_gsum[p * 512 + g_tid] = z;
            }
            BAR_SYNC(6, 512);                 // gsum stores drained; gpart free for next tt
            BAR_ARRIVE(1 + p, 1024);          // gsum[p] full
        }
    } else {
        // ================= R-warps: recurrence + epilogue =================
        for (int t = 0; t < T_STEPS; t++) {
            // ---- grid barrier (R threads only) ----
            BAR_SYNC(5, 512);
            if (tid == 0) {
                __threadfence();
                unsigned int gen = g_bar_gen;
                if (atomicAdd(&g_bar_count, 1u) == NCTA - 1u) {
                    atomicExch(&g_bar_count, 0u);
                    __threadfence();
                    g_bar_gen = gen + 1u;
                } else {
                    while (g_bar_gen == gen) { }
                }
                __threadfence();
            }
            BAR_SYNC(5, 512);

            const float* st  = g_stateT[t & 1];
            float*       stn = g_stateT[(t + 1) & 1];

            // ---- recurrent GEMM partials (cp.async pipelined) ----
            r_gemm_pipe(st, s_wh, s_rpart, s_stage + warp * 1024, warp, lane);

            BAR_SYNC(5, 512);                 // rpart ready
            BAR_SYNC(1 + (t & 1), 1024);      // gsum[t] ready

            // ---- reduce 16 R partials + gsum + bias, tanh ----
            const int o  = tid;               // 0..511
            const int jj = o & 7;
            const int b  = o >> 3;
            {
                const int pi = (b >> 1) * 16 + (b & 1) * 8 + jj;
                float z = s_bias[jj] + s_gsum[(t & 1) * 512 + o];
#pragma unroll
                for (int w = 0; w < NRWARPS; w++) z += s_rpart[w * 512 + pi];
                s_h[o] = tanhf(z);
            }
            BAR_ARRIVE(3 + (t & 1), 1024);    // gsum[t] consumed
            BAR_SYNC(5, 512);                 // s_h ready

            // ---- BatchNorm over batch dim: warps 0..7, column j0+c ----
            if (warp < 8) {
                int c = warp;
                float v1 = s_h[lane * 8 + c];
                float v2 = s_h[(lane + 32) * 8 + c];
                float sm = v1 + v2;
                float sq = v1 * v1 + v2 * v2;
#pragma unroll
                for (int off = 16; off; off >>= 1) {
                    sm += __shfl_xor_sync(0xFFFFFFFFu, sm, off);
                    sq += __shfl_xor_sync(0xFFFFFFFFu, sq, off);
                }
                float mu   = sm * (1.0f / 64.0f);
                float var  = sq * (1.0f / 64.0f) - mu * mu;
                float rstd = rsqrtf(var + BN_EPS);
                float o1 = (v1 - mu) * rstd;
                float o2 = (v2 - mu) * rstd;
                stn[(j0 + c) * B_DIM + lane]      = o1;
                stn[(j0 + c) * B_DIM + lane + 32] = o2;
                s_h[lane * 8 + c]        = o1;
                s_h[(lane + 32) * 8 + c] = o2;
            }
            BAR_SYNC(5, 512);

            // ---- write outputs (both tuple copies; fire-and-forget) ----
            {
                float v = s_h[o];
                size_t idx = (size_t)b * DH + j0 + jj;
                float* ob = out + (size_t)t * B_DIM * DH;
                ob[idx] = v;
                if (dup) (out + half + (size_t)t * B_DIM * DH)[idx] = v;
            }
        }
    }
}

// ---------------- launch ----------------
extern "C" void kernel_launch(void* const* d_in, const int* in_sizes, int n_in,
                              void* d_out, int out_size) {
    const float* x      = (const float*)d_in[0];  // [T][B][DIN]
    const float* state0 = (const float*)d_in[1];  // [1][B][DH]
    const float* Wx     = (const float*)d_in[2];  // [DIN][DH]
    const float* Wh     = (const float*)d_in[3];  // [DH][DH]
    const float* bias   = (const float*)d_in[4];  // [DH]
    float* out = (float*)d_out;

    // immediate (non-stream) call: legal during capture, identical every call
    cudaFuncSetAttribute(rnn_fused_kernel,
                         cudaFuncAttributeMaxDynamicSharedMemorySize, SMEM_BYTES);

    // XT = transpose(X) per timestep: [T][B][DIN] -> [T][DIN][B]
    {
        float* xt;
        cudaGetSymbolAddress((void**)&xt, g_xt);
        dim3 grid(DIN / 32, B_DIM / 32, T_STEPS);
        transpose_x_kernel<<<grid, dim3(32, 8)>>>(x, xt);
    }
    // fused persistent recurrence + decoupled input GEMM (cp.async state pipeline)
    rnn_fused_kernel<<<NCTA, NTHREADS, SMEM_BYTES>>>(state0, Wh, Wx, bias, out, out_size);
}